// round 12
// baseline (speedup 1.0000x reference)
#include <cuda_runtime.h>
#include <cuda_bf16.h>
#include <cstdint>

#define NN 50000
#define EE 800000
#define GG 64
#define HH 64
#define NB ((NN + 255) / 256)   // 196 scan chunks

// ---------------- scratch (device globals; no allocation allowed) ----------
__device__ __align__(16) int   g_degin_i[NN];
__device__ __align__(16) int   g_degout_i[NN];
__device__ __align__(16) int   g_rowptr[NN + 1];
__device__ __align__(16) int   g_cursor[NN];
__device__ __align__(16) int   g_blocksum[NB];
__device__ __align__(16) int   g_csr_src[EE];
__device__ __align__(16) float g_norm_src[NN];
__device__ __align__(16) float g_norm_dst[NN];
__device__ __align__(16) float g_hA[NN * HH];     // feature ping buffer
__device__ __align__(16) float g_hB[NN * HH];     // feature pong buffer
__device__ __align__(16) float g_agg1[NN * 4];    // layer-1 aggregation (4-wide)
__device__ __align__(16) float g_gsum[GG * HH];   // graph pooling sums
__device__ __align__(16) float g_gcnt[GG];

// grid barrier state (zero-initialized at module load; count always returns to 0,
// phase is monotonic and waits are RELATIVE to the value read at kernel entry,
// so graph replays are safe)
__device__ unsigned g_bar_count;
__device__ volatile unsigned g_bar_phase;

// ---------------- helpers ---------------------------------------------------
__device__ __forceinline__ void red4(float* p, float4 v) {
    asm volatile("red.global.add.v4.f32 [%0], {%1, %2, %3, %4};"
                 :: "l"(p), "f"(v.x), "f"(v.y), "f"(v.z), "f"(v.w) : "memory");
}

// grid-wide barrier: all gridDim.x blocks must be co-resident.
__device__ __forceinline__ void grid_sync(unsigned target) {
    __syncthreads();
    if (threadIdx.x == 0) {
        __threadfence();
        unsigned old = atomicAdd(&g_bar_count, 1u);
        if (old == gridDim.x - 1u) {
            atomicExch(&g_bar_count, 0u);
            __threadfence();
            g_bar_phase = target;              // release
        } else {
            while (g_bar_phase < target) { }   // spin (L2 volatile read)
        }
        __threadfence();                        // acquire
    }
    __syncthreads();
}

// layer body (R8 champion, verbatim semantics): one warp = 4 nodes.
__device__ __forceinline__ void layer_phase(
        const float* __restrict__ hin, float* __restrict__ hout,
        const int* __restrict__ gids, bool last,
        const float* Ws, const float* bs, float (*xs)[4][68],
        int warp, int half, int o4, int nb, int bid) {
    const float4* Ws4 = reinterpret_cast<const float4*>(Ws);
    const float4* h4 = reinterpret_cast<const float4*>(hin);
    const int* __restrict__ csr = g_csr_src;
    const int NQ = NN / 4;

    for (int quad = bid * 8 + warp; quad < NQ; quad += nb * 8) {
        // gather: this lane handles nodes (half) and (half+2) of the quad
#pragma unroll
        for (int g = 0; g < 2; g++) {
            int q = half + 2 * g;
            int n = quad * 4 + q;
            int e0 = g_rowptr[n], e1 = g_rowptr[n + 1];
            float4 acc = make_float4(0.f, 0.f, 0.f, 0.f);
            int e = e0;
            for (; e + 3 < e1; e += 4) {
                int s0 = csr[e], s1 = csr[e + 1], s2 = csr[e + 2], s3 = csr[e + 3];
                float4 v0 = h4[s0 * 16 + o4];
                float4 v1 = h4[s1 * 16 + o4];
                float4 v2 = h4[s2 * 16 + o4];
                float4 v3 = h4[s3 * 16 + o4];
                acc.x += (v0.x + v1.x) + (v2.x + v3.x);
                acc.y += (v0.y + v1.y) + (v2.y + v3.y);
                acc.z += (v0.z + v1.z) + (v2.z + v3.z);
                acc.w += (v0.w + v1.w) + (v2.w + v3.w);
            }
            for (; e < e1; e++) {
                float4 v = h4[csr[e] * 16 + o4];
                acc.x += v.x; acc.y += v.y; acc.z += v.z; acc.w += v.w;
            }
            float nd = g_norm_dst[n];
            acc.x *= nd; acc.y *= nd; acc.z *= nd; acc.w *= nd;
            reinterpret_cast<float4*>(&xs[warp][q][0])[o4] = acc;
        }
        __syncwarp();
        // GEMM: slice o4 for nodes q0=2*half, q1=2*half+1 (shared W loads)
        {
            int q0 = 2 * half;
            int n0 = quad * 4 + q0;
            int n1 = n0 + 1;
            float4 bb = reinterpret_cast<const float4*>(bs)[o4];
            float4 r0 = bb, r1 = bb;
            const float4* x0row = reinterpret_cast<const float4*>(&xs[warp][q0][0]);
            const float4* x1row = reinterpret_cast<const float4*>(&xs[warp][q0 + 1][0]);
#pragma unroll
            for (int k4 = 0; k4 < 16; k4++) {
                float4 x0v = x0row[k4];
                float4 x1v = x1row[k4];
#pragma unroll
                for (int j = 0; j < 4; j++) {
                    float4 w = Ws4[(k4 * 4 + j) * 16 + o4];
                    float a = (j == 0) ? x0v.x : (j == 1) ? x0v.y : (j == 2) ? x0v.z : x0v.w;
                    float c = (j == 0) ? x1v.x : (j == 1) ? x1v.y : (j == 2) ? x1v.z : x1v.w;
                    r0.x = fmaf(a, w.x, r0.x);
                    r0.y = fmaf(a, w.y, r0.y);
                    r0.z = fmaf(a, w.z, r0.z);
                    r0.w = fmaf(a, w.w, r0.w);
                    r1.x = fmaf(c, w.x, r1.x);
                    r1.y = fmaf(c, w.y, r1.y);
                    r1.z = fmaf(c, w.z, r1.z);
                    r1.w = fmaf(c, w.w, r1.w);
                }
            }
            r0.x = fmaxf(r0.x, 0.f); r0.y = fmaxf(r0.y, 0.f);
            r0.z = fmaxf(r0.z, 0.f); r0.w = fmaxf(r0.w, 0.f);
            r1.x = fmaxf(r1.x, 0.f); r1.y = fmaxf(r1.y, 0.f);
            r1.z = fmaxf(r1.z, 0.f); r1.w = fmaxf(r1.w, 0.f);
            if (!last) {
                float ns0 = g_norm_src[n0];
                float ns1 = g_norm_src[n1];
                r0.x *= ns0; r0.y *= ns0; r0.z *= ns0; r0.w *= ns0;
                r1.x *= ns1; r1.y *= ns1; r1.z *= ns1; r1.w *= ns1;
                reinterpret_cast<float4*>(hout)[n0 * 16 + o4] = r0;
                reinterpret_cast<float4*>(hout)[n1 * 16 + o4] = r1;
            } else {
                int g0 = gids[n0];
                int g1 = gids[n1];
                red4(&g_gsum[g0 * HH + o4 * 4], r0);
                red4(&g_gsum[g1 * HH + o4 * 4], r1);
            }
        }
        __syncwarp();
    }
}

// ---------------- the whole network in one persistent kernel -----------------
__global__ void __launch_bounds__(256, 4) mega_kernel(
        const int* __restrict__ src, const int* __restrict__ dst,
        const int* __restrict__ gids,
        const float* __restrict__ W1, const float* __restrict__ b1,
        const float* __restrict__ W2, const float* __restrict__ b2,
        const float* __restrict__ W3, const float* __restrict__ b3,
        const float* __restrict__ W4, const float* __restrict__ b4,
        const float* __restrict__ Wout, const float* __restrict__ bout,
        float* __restrict__ out) {
    __shared__ __align__(16) float Ws[HH * HH];
    __shared__ __align__(16) float bs[HH];
    __shared__ __align__(16) float xs[8][4][68];
    __shared__ int s_scan[256];

    const int tid = threadIdx.x;
    const int bid = blockIdx.x;
    const int nb = gridDim.x;
    const int gsz = nb * 256;
    const int idx = bid * 256 + tid;

    const int warp = tid >> 5;
    const int lane = tid & 31;
    const int half = lane >> 4;
    const int o4 = lane & 15;

    unsigned bar0 = 0;
    if (tid == 0) bar0 = g_bar_phase;   // relative base (replay-safe)

    // ---- P0: zero degrees + pooling buffers
    for (int i = idx; i < NN; i += gsz) { g_degin_i[i] = 0; g_degout_i[i] = 0; }
    for (int i = idx; i < GG * HH; i += gsz) g_gsum[i] = 0.f;
    for (int i = idx; i < GG; i += gsz) g_gcnt[i] = 0.f;
    grid_sync(bar0 + 1);

    // ---- P1: degree histogram
    for (int e = idx; e < EE; e += gsz) {
        atomicAdd(&g_degin_i[dst[e]], 1);
        atomicAdd(&g_degout_i[src[e]], 1);
    }
    grid_sync(bar0 + 2);

    // ---- P2: per-chunk exclusive scan (chunks 0..NB-1)
    if (bid < NB) {
        int n = bid * 256 + tid;
        int v = (n < NN) ? g_degin_i[n] : 0;
        s_scan[tid] = v;
        __syncthreads();
#pragma unroll
        for (int off = 1; off < 256; off <<= 1) {
            int add = (tid >= off) ? s_scan[tid - off] : 0;
            __syncthreads();
            s_scan[tid] += add;
            __syncthreads();
        }
        if (n < NN) g_rowptr[n] = s_scan[tid] - v;
        if (tid == 255) g_blocksum[bid] = s_scan[255];
    }
    grid_sync(bar0 + 3);

    // ---- P3: scan of chunk sums (block 0 only)
    if (bid == 0) {
        int v = (tid < NB) ? g_blocksum[tid] : 0;
        s_scan[tid] = v;
        __syncthreads();
#pragma unroll
        for (int off = 1; off < 256; off <<= 1) {
            int add = (tid >= off) ? s_scan[tid - off] : 0;
            __syncthreads();
            s_scan[tid] += add;
            __syncthreads();
        }
        if (tid < NB) g_blocksum[tid] = s_scan[tid] - v;
        if (tid == 0) g_rowptr[NN] = EE;
    }
    grid_sync(bar0 + 4);

    // ---- P4: finalize rowptr/cursors + features/norms
    for (int n = idx; n < NN; n += gsz) {
        int r = g_rowptr[n] + g_blocksum[n >> 8];
        g_rowptr[n] = r;
        g_cursor[n] = r;
        float di = (float)g_degin_i[n];
        float dout = (float)g_degout_i[n];
        float h1 = di;
        float h2 = (di - 3.f > 0.f) ? 1.f : 0.f;
        float h3 = 3.f / di;
        float h4 = (di - 4.f > 0.f) ? 1.f : 0.f;
        float ns = rsqrtf(fmaxf(dout, 1.f));
        float nd = rsqrtf(fmaxf(di, 1.f));
        g_norm_src[n] = ns;
        g_norm_dst[n] = nd;
        reinterpret_cast<float4*>(g_hA)[n] =
            make_float4(h1 * ns, h2 * ns, h3 * ns, h4 * ns);
        atomicAdd(&g_gcnt[gids[n]], 1.f);
    }
    grid_sync(bar0 + 5);

    // ---- P5: scatter edges into CSR
    for (int e = idx; e < EE; e += gsz) {
        int d = dst[e];
        int pos = atomicAdd(&g_cursor[d], 1);
        g_csr_src[pos] = src[e];
    }
    grid_sync(bar0 + 6);

    // ---- P6: layer-1 aggregation (4-wide)
    for (int n = idx; n < NN; n += gsz) {
        int e0 = g_rowptr[n], e1 = g_rowptr[n + 1];
        const float4* h4 = reinterpret_cast<const float4*>(g_hA);
        float4 acc = make_float4(0.f, 0.f, 0.f, 0.f);
        int e = e0;
        for (; e + 1 < e1; e += 2) {
            float4 v0 = h4[g_csr_src[e]];
            float4 v1 = h4[g_csr_src[e + 1]];
            acc.x += v0.x + v1.x; acc.y += v0.y + v1.y;
            acc.z += v0.z + v1.z; acc.w += v0.w + v1.w;
        }
        if (e < e1) {
            float4 v = h4[g_csr_src[e]];
            acc.x += v.x; acc.y += v.y; acc.z += v.z; acc.w += v.w;
        }
        reinterpret_cast<float4*>(g_agg1)[n] = acc;
    }
    grid_sync(bar0 + 7);

    // ---- P7: layer-1 node update -> g_hA (64-wide)
    for (int t = idx; t < NN * HH; t += gsz) {
        int n = t >> 6;
        int o = t & 63;
        float nd = g_norm_dst[n];
        float ns = g_norm_src[n];
        float4 x = reinterpret_cast<const float4*>(g_agg1)[n];
        float acc = b1[o];
        acc = fmaf(x.x * nd, W1[0 * HH + o], acc);
        acc = fmaf(x.y * nd, W1[1 * HH + o], acc);
        acc = fmaf(x.z * nd, W1[2 * HH + o], acc);
        acc = fmaf(x.w * nd, W1[3 * HH + o], acc);
        acc = fmaxf(acc, 0.f) * ns;
        g_hA[t] = acc;
    }
    grid_sync(bar0 + 8);

    // ---- P8: layer 2 (A -> B)
    {
        float4* Ws4 = reinterpret_cast<float4*>(Ws);
        const float4* Wg4 = reinterpret_cast<const float4*>(W2);
        for (int i = tid; i < HH * HH / 4; i += 256) Ws4[i] = Wg4[i];
        if (tid < HH) bs[tid] = b2[tid];
        __syncthreads();
        layer_phase(g_hA, g_hB, gids, false, Ws, bs, xs, warp, half, o4, nb, bid);
    }
    grid_sync(bar0 + 9);

    // ---- P9: layer 3 (B -> A)
    {
        float4* Ws4 = reinterpret_cast<float4*>(Ws);
        const float4* Wg4 = reinterpret_cast<const float4*>(W3);
        __syncthreads();   // all lanes done reading previous Ws
        for (int i = tid; i < HH * HH / 4; i += 256) Ws4[i] = Wg4[i];
        if (tid < HH) bs[tid] = b3[tid];
        __syncthreads();
        layer_phase(g_hB, g_hA, gids, false, Ws, bs, xs, warp, half, o4, nb, bid);
    }
    grid_sync(bar0 + 10);

    // ---- P10: layer 4 (A -> pool)
    {
        float4* Ws4 = reinterpret_cast<float4*>(Ws);
        const float4* Wg4 = reinterpret_cast<const float4*>(W4);
        __syncthreads();
        for (int i = tid; i < HH * HH / 4; i += 256) Ws4[i] = Wg4[i];
        if (tid < HH) bs[tid] = b4[tid];
        __syncthreads();
        layer_phase(g_hA, g_hB, gids, true, Ws, bs, xs, warp, half, o4, nb, bid);
    }
    grid_sync(bar0 + 11);

    // ---- P11: output head (first GG blocks)
    if (bid < GG) {
        if (tid < HH)
            bs[tid] = g_gsum[bid * HH + tid] * (1.f / g_gcnt[bid]) * Wout[tid];
        __syncthreads();
        if (tid < 32) {
            float x = bs[tid] + bs[tid + 32];
#pragma unroll
            for (int off = 16; off > 0; off >>= 1)
                x += __shfl_xor_sync(0xFFFFFFFF, x, off);
            if (tid == 0) out[bid] = 1.f / (1.f + expf(-(x + bout[0])));
        }
    }
}

// ---------------- launch -----------------------------------------------------
extern "C" void kernel_launch(void* const* d_in, const int* in_sizes, int n_in,
                              void* d_out, int out_size) {
    const int*   src  = (const int*)d_in[0];
    const int*   dst  = (const int*)d_in[1];
    const int*   gids = (const int*)d_in[2];
    const float* W1   = (const float*)d_in[3];
    const float* b1   = (const float*)d_in[4];
    const float* W2   = (const float*)d_in[5];
    const float* b2   = (const float*)d_in[6];
    const float* W3   = (const float*)d_in[7];
    const float* b3   = (const float*)d_in[8];
    const float* W4   = (const float*)d_in[9];
    const float* b4   = (const float*)d_in[10];
    const float* Wout = (const float*)d_in[11];
    const float* bout = (const float*)d_in[12];
    float* out = (float*)d_out;

    int smCount = 148;
    cudaDeviceGetAttribute(&smCount, cudaDevAttrMultiProcessorCount, 0);
    int maxBlk = 0;
    cudaOccupancyMaxActiveBlocksPerMultiprocessor(&maxBlk, mega_kernel, 256, 0);
    if (maxBlk < 1) maxBlk = 1;
    int grid = smCount * maxBlk;   // exactly one resident wave -> barrier is safe

    mega_kernel<<<grid, 256>>>(src, dst, gids, W1, b1, W2, b2, W3, b3,
                               W4, b4, Wout, bout, out);
}